// round 16
// baseline (speedup 1.0000x reference)
#include <cuda_runtime.h>
#include <cstdint>
#include <math.h>
#include <limits.h>

#define NB    512      // batch
#define NRBOX 18
#define DD    2048
#define NROBJ 16
#define KSEL  3
#define NCLS  174
#define NCAT  321
#define NCAND 8192               // NB * NROBJ
#define HCAND 4096               // candidates per half-block
#define GUM_PLANE 4194304u       // NB * NCAND
#define ORI_OFF 0
#define FEA_OFF 1048576          // NB*DD
#define LAB_OFF 4194304          // NB*DD + NB*KSEL*DD

// ---------------- scratch (static device globals; no allocation) ----------------
__device__ float g_pv[NB * 2 * KSEL];   // per-half best value
__device__ int   g_pc[NB * 2 * KSEL];   // per-half best candidate
__device__ int   g_nc[NB * 2];          // per-half candidate count
__device__ int   g_anyind[NB];          // any obj_indicator != 0 per row
__device__ int   g_slot[NB * KSEL];
__device__ float g_lam[NB];

// ---------------- Threefry-2x32 (20 rounds), matches jax.random ----------------
__host__ __forceinline__ uint32_t tf_rotl_h(uint32_t v, int r) {
    return (v << r) | (v >> (32 - r));
}

__host__ __forceinline__ void tf2x32_h(uint32_t k0, uint32_t k1,
                                       uint32_t x0, uint32_t x1,
                                       uint32_t& o0, uint32_t& o1) {
    uint32_t k2 = k0 ^ k1 ^ 0x1BD11BDAu;
    x0 += k0; x1 += k1;
#define TFRH(r) { x0 += x1; x1 = tf_rotl_h(x1, r); x1 ^= x0; }
    TFRH(13) TFRH(15) TFRH(26) TFRH(6)
    x0 += k1; x1 += k2 + 1u;
    TFRH(17) TFRH(29) TFRH(16) TFRH(24)
    x0 += k2; x1 += k0 + 2u;
    TFRH(13) TFRH(15) TFRH(26) TFRH(6)
    x0 += k0; x1 += k1 + 3u;
    TFRH(17) TFRH(29) TFRH(16) TFRH(24)
    x0 += k1; x1 += k2 + 4u;
    TFRH(13) TFRH(15) TFRH(26) TFRH(6)
    x0 += k2; x1 += k0 + 5u;
#undef TFRH
    o0 = x0; o1 = x1;
}

// Integer add forced onto the FMA pipe: d = a*one + b (one is an opaque reg == 1).
__device__ __forceinline__ uint32_t iadd_fma(uint32_t a, uint32_t b, uint32_t one) {
    uint32_t d;
    asm("mad.lo.u32 %0, %1, %2, %3;" : "=r"(d) : "r"(a), "r"(one), "r"(b));
    return d;
}

struct TFKeys {
    uint32_t a0, b0, a1, b1, a2, b2, a3, b3, a4, b4, a5, b5;
};

__device__ __forceinline__ TFKeys tf_make_keys(uint32_t k0, uint32_t k1) {
    uint32_t k2 = k0 ^ k1 ^ 0x1BD11BDAu;
    TFKeys K;
    K.a0 = k0;      K.b0 = k1;
    K.a1 = k1;      K.b1 = k2 + 1u;
    K.a2 = k2;      K.b2 = k0 + 2u;
    K.a3 = k0;      K.b3 = k1 + 3u;
    K.a4 = k1;      K.b4 = k2 + 4u;
    K.a5 = k2;      K.b5 = k0 + 5u;
    return K;
}

__device__ __forceinline__ uint32_t tf_bits_fast(const TFKeys& K, uint32_t m, uint32_t one) {
    uint32_t x0 = K.a0;                   // 0 + k0
    uint32_t x1 = iadd_fma(m, K.b0, one); // m + k1
#define TFRI(r) { x0 = iadd_fma(x1, x0, one); x1 = __funnelshift_l(x1, x1, r); x1 ^= x0; }
#define INJI(a, b) { x0 = iadd_fma(a, x0, one); x1 = iadd_fma(b, x1, one); }
    TFRI(13) TFRI(15) TFRI(26) TFRI(6)
    INJI(K.a1, K.b1)
    TFRI(17) TFRI(29) TFRI(16) TFRI(24)
    INJI(K.a2, K.b2)
    TFRI(13) TFRI(15) TFRI(26) TFRI(6)
    INJI(K.a3, K.b3)
    TFRI(17) TFRI(29) TFRI(16) TFRI(24)
    INJI(K.a4, K.b4)
    TFRI(13) TFRI(15) TFRI(26) TFRI(6)
    INJI(K.a5, K.b5)
#undef TFRI
#undef INJI
    return x0 ^ x1;
}

__device__ __forceinline__ float bits_to_unit(uint32_t b) {
    return __uint_as_float((b >> 9) | 0x3f800000u) - 1.0f;
}

// one candidate, all 3 gumbel planes; branchless MUFU-log2 key (ordering == XLA's)
__device__ __forceinline__ void eval_cand(uint32_t p, const TFKeys& K1,
                                          const float* __restrict__ s_rw,
                                          uint32_t rowbase, uint32_t one,
                                          float* bv, int* bi) {
    int c = (int)(p & 8191u);
    float rw = s_rw[p >> 13];
    uint32_t m = rowbase + (uint32_t)c;
#pragma unroll
    for (int k = 0; k < KSEL; k++) {
        uint32_t b = tf_bits_fast(K1, m + (uint32_t)k * GUM_PLANE, one);
        float f = __uint_as_float((b >> 9) | 0x3f800000u) - 1.0f;  // u pre-clamp
        float u = fmaxf(f, 1.17549435e-38f);
        float v = -__log2f(u) * rw;                                // MUFU.LG2, no branches
        if (v < bv[k]) { bv[k] = v; bi[k] = c; }                   // list is c-ascending: first-min kept
    }
}

// ---------------- kernel 1: selection (half-row blocks, 2x-unrolled branchless loop) ----------------
__global__ __launch_bounds__(256) void select_kernel(
    const float* __restrict__ cooc,
    const int*   __restrict__ obj_cat,
    const int*   __restrict__ obj_ind,
    const int*   __restrict__ labels,
    uint32_t r1x, uint32_t r1y,
    uint32_t r2x, uint32_t r2y,
    uint32_t ksx, uint32_t ksy,
    uint32_t one)
{
    __shared__ float    s_rw[NCAT];       // 1/w, or -1 sentinel
    __shared__ uint32_t s_list[HCAND];    // packed: c | (cat<<13)
    __shared__ int      s_cnt;
    __shared__ float    s_wv[KSEL][8];
    __shared__ int      s_wi[KSEL][8];

    const int i    = blockIdx.x >> 1;
    const int half = blockIdx.x & 1;
    const int tid  = threadIdx.x;
    const int lane = tid & 31;
    const int wid  = tid >> 5;
    if (tid == 0) s_cnt = 0;

    const int lab = labels[i];
    for (int t = tid; t < NCAT; t += 256) {
        float w = cooc[lab * NCAT + t];
        s_rw[t] = (w > 0.0f) ? (1.0f / w) : -1.0f;
    }
    __syncthreads();

    // phase A: compact passing candidates of this half (warp-aggregated append;
    // rounds proceed in ascending c, so the list is globally c-ascending)
    const int cbase = half * HCAND;
#pragma unroll 4
    for (int c0 = tid; c0 < HCAND; c0 += 256) {
        int c   = cbase + c0;
        int j   = c >> 4;
        int cat = __ldg(&obj_cat[j * NRBOX + 2 + (c & 15)]);
        bool pass = (j != i) && (s_rw[cat] > 0.0f);
        unsigned mask = __ballot_sync(0xffffffffu, pass);
        int base = 0;
        if (lane == 0 && mask) base = atomicAdd(&s_cnt, __popc(mask));
        base = __shfl_sync(0xffffffffu, base, 0);
        if (pass) {
            int rank = __popc(mask & ((1u << lane) - 1u));
            s_list[base + rank] = (uint32_t)c | ((uint32_t)cat << 13);
        }
    }
    __syncthreads();
    const int nc = s_cnt;

    // phase B: 2x-unrolled branchless loop
    const TFKeys K1 = tf_make_keys(r1x, r1y);
    float bv[KSEL] = {INFINITY, INFINITY, INFINITY};
    int   bi[KSEL] = {INT_MAX, INT_MAX, INT_MAX};
    const uint32_t rowbase = (uint32_t)i * (uint32_t)NCAND;

    int t = tid;
    for (; t + 256 < nc; t += 512) {
        uint32_t p0 = s_list[t];
        uint32_t p1 = s_list[t + 256];
        eval_cand(p0, K1, s_rw, rowbase, one, bv, bi);
        eval_cand(p1, K1, s_rw, rowbase, one, bv, bi);
    }
    if (t < nc) {
        eval_cand(s_list[t], K1, s_rw, rowbase, one, bv, bi);
    }

    // warp argmin, then cross-warp (8 entries)
#pragma unroll
    for (int k = 0; k < KSEL; k++) {
#pragma unroll
        for (int off = 16; off > 0; off >>= 1) {
            float ov = __shfl_down_sync(0xffffffffu, bv[k], off);
            int   oi = __shfl_down_sync(0xffffffffu, bi[k], off);
            if (ov < bv[k] || (ov == bv[k] && oi < bi[k])) { bv[k] = ov; bi[k] = oi; }
        }
        if (lane == 0) { s_wv[k][wid] = bv[k]; s_wi[k][wid] = bi[k]; }
    }
    __syncthreads();

    if (tid < 32) {
#pragma unroll
        for (int k = 0; k < KSEL; k++) {
            float v = (lane < 8) ? s_wv[k][lane] : INFINITY;
            int  ix = (lane < 8) ? s_wi[k][lane] : INT_MAX;
#pragma unroll
            for (int off = 4; off > 0; off >>= 1) {
                float ov = __shfl_down_sync(0xffffffffu, v, off);
                int   oi = __shfl_down_sync(0xffffffffu, ix, off);
                if (ov < v || (ov == v && oi < ix)) { v = ov; ix = oi; }
            }
            if (lane == 0) {
                g_pv[(i * 2 + half) * KSEL + k] = v;
                g_pc[(i * 2 + half) * KSEL + k] = ix;
            }
        }
        if (lane == 0) g_nc[i * 2 + half] = nc;
    }

    if (half == 0) {
        if (tid >= 64 && tid < 64 + KSEL) {
            int k = tid - 64;
            const TFKeys Ks = tf_make_keys(ksx, ksy);
            uint32_t sb = tf_bits_fast(Ks, (uint32_t)(i * KSEL + k), one);
            g_slot[i * KSEL + k] = (int)(sb & 15u);
        }
        if (tid == 96) {
            const TFKeys K2 = tf_make_keys(r2x, r2y);
            uint32_t lb = tf_bits_fast(K2, (uint32_t)i, one);
            g_lam[i] = bits_to_unit(lb);
        }
        if (tid == 97) {
            bool anyind = false;
#pragma unroll
            for (int o = 0; o < NROBJ; o++) anyind |= (__ldg(&obj_ind[i * NRBOX + 2 + o]) != 0);
            g_anyind[i] = anyind ? 1 : 0;
        }
    }
}

// ---------------- kernel 2: fused mean + mix (d-split: two blocks per row, slim prologue) ----------------
__global__ __launch_bounds__(256) void meanmix_kernel(const float* __restrict__ fea,
                                                      const int* __restrict__ labels,
                                                      float* __restrict__ out) {
    const int i    = blockIdx.x >> 1;
    const int half = blockIdx.x & 1;
    const int tid  = threadIdx.x;
    const int d    = half * 256 + tid;   // float4 column 0..511

    // slim prologue: merge halves -> final selections (all loads L2-hot from select)
    const float lam = g_lam[i];
    const float oml = 1.0f - lam;
    int bsel[KSEL], osel[KSEL], slot[KSEL];
#pragma unroll
    for (int k = 0; k < KSEL; k++) {
        float v0 = g_pv[(i * 2 + 0) * KSEL + k];
        float v1 = g_pv[(i * 2 + 1) * KSEL + k];
        int   c0 = g_pc[(i * 2 + 0) * KSEL + k];
        int   c1 = g_pc[(i * 2 + 1) * KSEL + k];
        int c = (v1 < v0 || (v1 == v0 && c1 < c0)) ? c1 : c0;
        if (c == INT_MAX) c = 0;
        bsel[k] = c >> 4;
        osel[k] = c & 15;
        slot[k] = g_slot[i * KSEL + k];
    }
    const bool hc = ((g_nc[i * 2] + g_nc[i * 2 + 1]) > 0) && (g_anyind[i] != 0);

    const float4* base = (const float4*)(fea + (size_t)i * NRBOX * DD);

    float4 s18 = make_float4(0.f, 0.f, 0.f, 0.f);
    float4 s16 = make_float4(0.f, 0.f, 0.f, 0.f);
#pragma unroll
    for (int j = 0; j < NRBOX; j++) {
        float4 v = base[j * 512 + d];
        s18.x += v.x; s18.y += v.y; s18.z += v.z; s18.w += v.w;
        if (j >= 2) { s16.x += v.x; s16.y += v.y; s16.z += v.z; s16.w += v.w; }
    }
    const float i18 = 1.0f / 18.0f, i16 = 1.0f / 16.0f;
    ((float4*)(out + ORI_OFF + (size_t)i * DD))[d] =
        make_float4(s18.x * i18, s18.y * i18, s18.z * i18, s18.w * i18);
    float4 fb = make_float4(s16.x * i16, s16.y * i16, s16.z * i16, s16.w * i16);

#pragma unroll
    for (int k = 0; k < KSEL; k++) {
        float4* fout = (float4*)(out + FEA_OFF + (size_t)(i * KSEL + k) * DD);
        if (hc) {
            float4 a = base[(2 + slot[k]) * 512 + d];   // L1/L2-hot (loaded in j-loop)
            float4 b = ((const float4*)(fea + (size_t)(bsel[k] * NRBOX + 2 + osel[k]) * DD))[d];
            fout[d] = make_float4(a.x * lam + b.x * oml, a.y * lam + b.y * oml,
                                  a.z * lam + b.z * oml, a.w * lam + b.w * oml);
        } else {
            fout[d] = fb;
        }
    }

    // labels (half 0 only)
    if (half == 0 && tid < NCLS) {
        const int li = labels[i];
#pragma unroll
        for (int k = 0; k < KSEL; k++) {
            float* lout = out + LAB_OFF + (size_t)(i * KSEL + k) * NCLS;
            float a = (tid == li) ? 1.0f : 0.0f;
            if (hc) {
                float c2 = (tid == labels[bsel[k]]) ? 1.0f : 0.0f;
                lout[tid] = a * lam + c2 * oml;
            } else {
                lout[tid] = a;
            }
        }
    }
}

// ---------------- launcher ----------------
extern "C" void kernel_launch(void* const* d_in, const int* in_sizes, int n_in,
                              void* d_out, int out_size) {
    const float* obj_fea = (const float*)d_in[0];
    const float* cooc    = (const float*)d_in[1];
    const int*   obj_ind = (const int*)d_in[2];
    const int*   obj_cat = (const int*)d_in[3];
    const int*   labels  = (const int*)d_in[4];
    float* out = (float*)d_out;

    uint32_t r1x, r1y, r2x, r2y, r3x, r3y, ksx, ksy;
    tf2x32_h(0u, 42u, 0u, 0u, r1x, r1y);
    tf2x32_h(0u, 42u, 0u, 1u, r2x, r2y);
    tf2x32_h(0u, 42u, 0u, 2u, r3x, r3y);
    tf2x32_h(r3x, r3y, 0u, 1u, ksx, ksy);

    select_kernel<<<NB * 2, 256>>>(cooc, obj_cat, obj_ind, labels,
                                   r1x, r1y, r2x, r2y, ksx, ksy, 1u);
    meanmix_kernel<<<NB * 2, 256>>>(obj_fea, labels, out);
}

// round 17
// speedup vs baseline: 1.0308x; 1.0308x over previous
#include <cuda_runtime.h>
#include <cstdint>
#include <math.h>
#include <limits.h>

#define NB    512      // batch
#define NRBOX 18
#define DD    2048
#define NROBJ 16
#define KSEL  3
#define NCLS  174
#define NCAT  321
#define NCAND 8192               // NB * NROBJ
#define HCAND 4096               // candidates per half-block
#define GUM_PLANE 4194304u       // NB * NCAND
#define ORI_OFF 0
#define FEA_OFF 1048576          // NB*DD
#define LAB_OFF 4194304          // NB*DD + NB*KSEL*DD

// ---------------- scratch (static device globals; no allocation) ----------------
__device__ float g_pv[NB * 2 * KSEL];   // per-half best value
__device__ int   g_pc[NB * 2 * KSEL];   // per-half best candidate
__device__ int   g_nc[NB * 2];          // per-half candidate count
__device__ int   g_anyind[NB];          // any obj_indicator != 0 per row
__device__ int   g_slot[NB * KSEL];
__device__ float g_lam[NB];

// ---------------- Threefry-2x32 (20 rounds), matches jax.random ----------------
__host__ __forceinline__ uint32_t tf_rotl_h(uint32_t v, int r) {
    return (v << r) | (v >> (32 - r));
}

__host__ __forceinline__ void tf2x32_h(uint32_t k0, uint32_t k1,
                                       uint32_t x0, uint32_t x1,
                                       uint32_t& o0, uint32_t& o1) {
    uint32_t k2 = k0 ^ k1 ^ 0x1BD11BDAu;
    x0 += k0; x1 += k1;
#define TFRH(r) { x0 += x1; x1 = tf_rotl_h(x1, r); x1 ^= x0; }
    TFRH(13) TFRH(15) TFRH(26) TFRH(6)
    x0 += k1; x1 += k2 + 1u;
    TFRH(17) TFRH(29) TFRH(16) TFRH(24)
    x0 += k2; x1 += k0 + 2u;
    TFRH(13) TFRH(15) TFRH(26) TFRH(6)
    x0 += k0; x1 += k1 + 3u;
    TFRH(17) TFRH(29) TFRH(16) TFRH(24)
    x0 += k1; x1 += k2 + 4u;
    TFRH(13) TFRH(15) TFRH(26) TFRH(6)
    x0 += k2; x1 += k0 + 5u;
#undef TFRH
    o0 = x0; o1 = x1;
}

// Integer add forced onto the FMA pipe: d = a*one + b (one is an opaque reg == 1).
__device__ __forceinline__ uint32_t iadd_fma(uint32_t a, uint32_t b, uint32_t one) {
    uint32_t d;
    asm("mad.lo.u32 %0, %1, %2, %3;" : "=r"(d) : "r"(a), "r"(one), "r"(b));
    return d;
}

struct TFKeys {
    uint32_t a0, b0, a1, b1, a2, b2, a3, b3, a4, b4, a5, b5;
};

__device__ __forceinline__ TFKeys tf_make_keys(uint32_t k0, uint32_t k1) {
    uint32_t k2 = k0 ^ k1 ^ 0x1BD11BDAu;
    TFKeys K;
    K.a0 = k0;      K.b0 = k1;
    K.a1 = k1;      K.b1 = k2 + 1u;
    K.a2 = k2;      K.b2 = k0 + 2u;
    K.a3 = k0;      K.b3 = k1 + 3u;
    K.a4 = k1;      K.b4 = k2 + 4u;
    K.a5 = k2;      K.b5 = k0 + 5u;
    return K;
}

__device__ __forceinline__ uint32_t tf_bits_fast(const TFKeys& K, uint32_t m, uint32_t one) {
    uint32_t x0 = K.a0;                   // 0 + k0
    uint32_t x1 = iadd_fma(m, K.b0, one); // m + k1
#define TFRI(r) { x0 = iadd_fma(x1, x0, one); x1 = __funnelshift_l(x1, x1, r); x1 ^= x0; }
#define INJI(a, b) { x0 = iadd_fma(a, x0, one); x1 = iadd_fma(b, x1, one); }
    TFRI(13) TFRI(15) TFRI(26) TFRI(6)
    INJI(K.a1, K.b1)
    TFRI(17) TFRI(29) TFRI(16) TFRI(24)
    INJI(K.a2, K.b2)
    TFRI(13) TFRI(15) TFRI(26) TFRI(6)
    INJI(K.a3, K.b3)
    TFRI(17) TFRI(29) TFRI(16) TFRI(24)
    INJI(K.a4, K.b4)
    TFRI(13) TFRI(15) TFRI(26) TFRI(6)
    INJI(K.a5, K.b5)
#undef TFRI
#undef INJI
    return x0 ^ x1;
}

__device__ __forceinline__ float bits_to_unit(uint32_t b) {
    return __uint_as_float((b >> 9) | 0x3f800000u) - 1.0f;
}

// one candidate, all 3 gumbel planes; branchless MUFU-log2 key (ordering == XLA's)
__device__ __forceinline__ void eval_cand(uint32_t p, const TFKeys& K1,
                                          const float* __restrict__ s_rw,
                                          uint32_t rowbase, uint32_t one,
                                          float* bv, int* bi) {
    int c = (int)(p & 8191u);
    float rw = s_rw[p >> 13];
    uint32_t m = rowbase + (uint32_t)c;
#pragma unroll
    for (int k = 0; k < KSEL; k++) {
        uint32_t b = tf_bits_fast(K1, m + (uint32_t)k * GUM_PLANE, one);
        float f = __uint_as_float((b >> 9) | 0x3f800000u) - 1.0f;  // u pre-clamp
        float u = fmaxf(f, 1.17549435e-38f);
        float v = -__log2f(u) * rw;                                // MUFU.LG2, no branches
        if (v < bv[k]) { bv[k] = v; bi[k] = c; }                   // list is c-ascending: first-min kept
    }
}

// ---------------- kernel 1: selection (half-row blocks, 2x-unrolled branchless loop) ----------------
__global__ __launch_bounds__(256) void select_kernel(
    const float* __restrict__ cooc,
    const int*   __restrict__ obj_cat,
    const int*   __restrict__ obj_ind,
    const int*   __restrict__ labels,
    uint32_t r1x, uint32_t r1y,
    uint32_t r2x, uint32_t r2y,
    uint32_t ksx, uint32_t ksy,
    uint32_t one)
{
    __shared__ float    s_rw[NCAT];       // 1/w, or -1 sentinel
    __shared__ uint32_t s_list[HCAND];    // packed: c | (cat<<13)
    __shared__ int      s_cnt;
    __shared__ float    s_wv[KSEL][8];
    __shared__ int      s_wi[KSEL][8];

    const int i    = blockIdx.x >> 1;
    const int half = blockIdx.x & 1;
    const int tid  = threadIdx.x;
    const int lane = tid & 31;
    const int wid  = tid >> 5;
    if (tid == 0) s_cnt = 0;

    const int lab = labels[i];
    for (int t = tid; t < NCAT; t += 256) {
        float w = cooc[lab * NCAT + t];
        s_rw[t] = (w > 0.0f) ? (1.0f / w) : -1.0f;
    }
    __syncthreads();

    // phase A: compact passing candidates of this half (warp-aggregated append;
    // rounds proceed in ascending c, so the list is globally c-ascending)
    const int cbase = half * HCAND;
#pragma unroll 4
    for (int c0 = tid; c0 < HCAND; c0 += 256) {
        int c   = cbase + c0;
        int j   = c >> 4;
        int cat = __ldg(&obj_cat[j * NRBOX + 2 + (c & 15)]);
        bool pass = (j != i) && (s_rw[cat] > 0.0f);
        unsigned mask = __ballot_sync(0xffffffffu, pass);
        int base = 0;
        if (lane == 0 && mask) base = atomicAdd(&s_cnt, __popc(mask));
        base = __shfl_sync(0xffffffffu, base, 0);
        if (pass) {
            int rank = __popc(mask & ((1u << lane) - 1u));
            s_list[base + rank] = (uint32_t)c | ((uint32_t)cat << 13);
        }
    }
    __syncthreads();
    const int nc = s_cnt;

    // phase B: 2x-unrolled branchless loop
    const TFKeys K1 = tf_make_keys(r1x, r1y);
    float bv[KSEL] = {INFINITY, INFINITY, INFINITY};
    int   bi[KSEL] = {INT_MAX, INT_MAX, INT_MAX};
    const uint32_t rowbase = (uint32_t)i * (uint32_t)NCAND;

    int t = tid;
    for (; t + 256 < nc; t += 512) {
        uint32_t p0 = s_list[t];
        uint32_t p1 = s_list[t + 256];
        eval_cand(p0, K1, s_rw, rowbase, one, bv, bi);
        eval_cand(p1, K1, s_rw, rowbase, one, bv, bi);
    }
    if (t < nc) {
        eval_cand(s_list[t], K1, s_rw, rowbase, one, bv, bi);
    }

    // warp argmin, then cross-warp (8 entries)
#pragma unroll
    for (int k = 0; k < KSEL; k++) {
#pragma unroll
        for (int off = 16; off > 0; off >>= 1) {
            float ov = __shfl_down_sync(0xffffffffu, bv[k], off);
            int   oi = __shfl_down_sync(0xffffffffu, bi[k], off);
            if (ov < bv[k] || (ov == bv[k] && oi < bi[k])) { bv[k] = ov; bi[k] = oi; }
        }
        if (lane == 0) { s_wv[k][wid] = bv[k]; s_wi[k][wid] = bi[k]; }
    }
    __syncthreads();

    if (tid < 32) {
#pragma unroll
        for (int k = 0; k < KSEL; k++) {
            float v = (lane < 8) ? s_wv[k][lane] : INFINITY;
            int  ix = (lane < 8) ? s_wi[k][lane] : INT_MAX;
#pragma unroll
            for (int off = 4; off > 0; off >>= 1) {
                float ov = __shfl_down_sync(0xffffffffu, v, off);
                int   oi = __shfl_down_sync(0xffffffffu, ix, off);
                if (ov < v || (ov == v && oi < ix)) { v = ov; ix = oi; }
            }
            if (lane == 0) {
                g_pv[(i * 2 + half) * KSEL + k] = v;
                g_pc[(i * 2 + half) * KSEL + k] = ix;
            }
        }
        if (lane == 0) g_nc[i * 2 + half] = nc;
    }

    if (half == 0) {
        if (tid >= 64 && tid < 64 + KSEL) {
            int k = tid - 64;
            const TFKeys Ks = tf_make_keys(ksx, ksy);
            uint32_t sb = tf_bits_fast(Ks, (uint32_t)(i * KSEL + k), one);
            g_slot[i * KSEL + k] = (int)(sb & 15u);
        }
        if (tid == 96) {
            const TFKeys K2 = tf_make_keys(r2x, r2y);
            uint32_t lb = tf_bits_fast(K2, (uint32_t)i, one);
            g_lam[i] = bits_to_unit(lb);
        }
        if (tid == 97) {
            bool anyind = false;
#pragma unroll
            for (int o = 0; o < NROBJ; o++) anyind |= (__ldg(&obj_ind[i * NRBOX + 2 + o]) != 0);
            g_anyind[i] = anyind ? 1 : 0;
        }
    }
}

// ---------------- kernel 2: fused mean + mix (one block per row, R14 shape, slim prologue) ----------------
__global__ __launch_bounds__(256) void meanmix_kernel(const float* __restrict__ fea,
                                                      const int* __restrict__ labels,
                                                      float* __restrict__ out) {
    const int i   = blockIdx.x;
    const int tid = threadIdx.x;

    // slim prologue: merge halves -> final selections (all loads L2-hot from select)
    const float lam = g_lam[i];
    const float oml = 1.0f - lam;
    int bsel[KSEL], osel[KSEL], slot[KSEL];
#pragma unroll
    for (int k = 0; k < KSEL; k++) {
        float v0 = g_pv[(i * 2 + 0) * KSEL + k];
        float v1 = g_pv[(i * 2 + 1) * KSEL + k];
        int   c0 = g_pc[(i * 2 + 0) * KSEL + k];
        int   c1 = g_pc[(i * 2 + 1) * KSEL + k];
        int c = (v1 < v0 || (v1 == v0 && c1 < c0)) ? c1 : c0;
        if (c == INT_MAX) c = 0;
        bsel[k] = c >> 4;
        osel[k] = c & 15;
        slot[k] = g_slot[i * KSEL + k];
    }
    const bool hc = ((g_nc[i * 2] + g_nc[i * 2 + 1]) > 0) && (g_anyind[i] != 0);

    const float4* base = (const float4*)(fea + (size_t)i * NRBOX * DD);

#pragma unroll
    for (int it = 0; it < 2; it++) {
        const int d = tid + it * 256;        // float4 column 0..511
        float4 s18 = make_float4(0.f, 0.f, 0.f, 0.f);
        float4 s16 = make_float4(0.f, 0.f, 0.f, 0.f);
#pragma unroll
        for (int j = 0; j < NRBOX; j++) {
            float4 v = base[j * 512 + d];
            s18.x += v.x; s18.y += v.y; s18.z += v.z; s18.w += v.w;
            if (j >= 2) { s16.x += v.x; s16.y += v.y; s16.z += v.z; s16.w += v.w; }
        }
        const float i18 = 1.0f / 18.0f, i16 = 1.0f / 16.0f;
        ((float4*)(out + ORI_OFF + (size_t)i * DD))[d] =
            make_float4(s18.x * i18, s18.y * i18, s18.z * i18, s18.w * i18);
        float4 fb = make_float4(s16.x * i16, s16.y * i16, s16.z * i16, s16.w * i16);

#pragma unroll
        for (int k = 0; k < KSEL; k++) {
            float4* fout = (float4*)(out + FEA_OFF + (size_t)(i * KSEL + k) * DD);
            if (hc) {
                float4 a = base[(2 + slot[k]) * 512 + d];   // L1-hot (loaded in j-loop)
                float4 b = ((const float4*)(fea + (size_t)(bsel[k] * NRBOX + 2 + osel[k]) * DD))[d];
                fout[d] = make_float4(a.x * lam + b.x * oml, a.y * lam + b.y * oml,
                                      a.z * lam + b.z * oml, a.w * lam + b.w * oml);
            } else {
                fout[d] = fb;
            }
        }
    }

    // labels
    if (tid < NCLS) {
        const int li = labels[i];
#pragma unroll
        for (int k = 0; k < KSEL; k++) {
            float* lout = out + LAB_OFF + (size_t)(i * KSEL + k) * NCLS;
            float a = (tid == li) ? 1.0f : 0.0f;
            if (hc) {
                float c2 = (tid == labels[bsel[k]]) ? 1.0f : 0.0f;
                lout[tid] = a * lam + c2 * oml;
            } else {
                lout[tid] = a;
            }
        }
    }
}

// ---------------- launcher ----------------
extern "C" void kernel_launch(void* const* d_in, const int* in_sizes, int n_in,
                              void* d_out, int out_size) {
    const float* obj_fea = (const float*)d_in[0];
    const float* cooc    = (const float*)d_in[1];
    const int*   obj_ind = (const int*)d_in[2];
    const int*   obj_cat = (const int*)d_in[3];
    const int*   labels  = (const int*)d_in[4];
    float* out = (float*)d_out;

    uint32_t r1x, r1y, r2x, r2y, r3x, r3y, ksx, ksy;
    tf2x32_h(0u, 42u, 0u, 0u, r1x, r1y);
    tf2x32_h(0u, 42u, 0u, 1u, r2x, r2y);
    tf2x32_h(0u, 42u, 0u, 2u, r3x, r3y);
    tf2x32_h(r3x, r3y, 0u, 1u, ksx, ksy);

    select_kernel<<<NB * 2, 256>>>(cooc, obj_cat, obj_ind, labels,
                                   r1x, r1y, r2x, r2y, ksx, ksy, 1u);
    meanmix_kernel<<<NB, 256>>>(obj_fea, labels, out);
}